// round 16
// baseline (speedup 1.0000x reference)
#include <cuda_runtime.h>
#include <math.h>
#include <stdint.h>

#define NN    10000
#define HH    4
#define FF    128
#define HF    (HH*FF)      // 512
#define EE    320000
#define ET    (EE+NN)      // 330000 edges incl self-loops
#define SLOPE 0.2f
#define SPLITK 8
#define SPLITK_S 2

// ---------------- scratch (device globals; no allocation allowed) ----------
__device__ float g_hp  [(size_t)NN*HF];   // projected features [N,H,F]
__device__ float g_x   [(size_t)NN*FF];   // inter-layer features [N,F]
__device__ float g_z   [(size_t)NN*FF];   // encoder output z [N,F]
__device__ float g_als [NN*HH];
__device__ float g_ald [NN*HH];
__device__ float g_eval[(size_t)ET*HH];   // per-edge exp values (CSR order)
__device__ int   g_is64;                  // edge_index dtype flag
// CSR by destination node
__device__ int   g_deg [NN];
__device__ int   g_off [NN+1];
__device__ int   g_cur [NN];
__device__ int   g_eid [ET];
// split-K partial sums
__device__ float g_part[(size_t)SPLITK*NN*HF];

// --------- edge-index dtype sniffer ----------------------------------------
__global__ void detect_ei_kernel(const int* __restrict__ ei32)
{
    __shared__ int any;
    if (threadIdx.x == 0) any = 0;
    __syncthreads();
    for (int i = threadIdx.x; i < 4096; i += blockDim.x)
        if (ei32[2 * i + 1] != 0) atomicOr(&any, 1);
    __syncthreads();
    if (threadIdx.x == 0) g_is64 = (any == 0);
}

__device__ __forceinline__ void edge_sd(const int* __restrict__ ei32, int e,
                                        int& s, int& d)
{
    if (e >= EE) { s = d = e - EE; return; }          // self-loop
    if (g_is64) { s = ei32[2 * e]; d = ei32[2 * (EE + e)]; }
    else        { s = ei32[e];     d = ei32[EE + e]; }
}

__device__ __forceinline__ bool valid_nd(int s, int d)
{
    return ((unsigned)s < NN) && ((unsigned)d < NN);
}

// ---------------- CSR construction ------------------------------------------
__global__ void csr_zero_kernel()
{
    const int n = blockIdx.x * blockDim.x + threadIdx.x;
    if (n < NN) g_deg[n] = 0;
}

__global__ void csr_hist_kernel(const int* __restrict__ ei)
{
    const int e = blockIdx.x * blockDim.x + threadIdx.x;
    if (e >= ET) return;
    int s, d; edge_sd(ei, e, s, d);
    if (valid_nd(s, d)) atomicAdd(&g_deg[d], 1);
}

__global__ void csr_scan_kernel()
{
    __shared__ int warp_sums[32];
    const int tid  = threadIdx.x;          // 1024 threads
    const int lane = tid & 31, wid = tid >> 5;
    const int base = tid * 10;

    int local[10];
    int sum = 0;
    #pragma unroll
    for (int k = 0; k < 10; k++) {
        const int n = base + k;
        const int v = (n < NN) ? g_deg[n] : 0;
        local[k] = sum;
        sum += v;
    }
    int x = sum;
    #pragma unroll
    for (int o = 1; o < 32; o <<= 1) {
        const int y = __shfl_up_sync(0xffffffffu, x, o);
        if (lane >= o) x += y;
    }
    if (lane == 31) warp_sums[wid] = x;
    __syncthreads();
    if (wid == 0) {
        int w = warp_sums[lane];
        #pragma unroll
        for (int o = 1; o < 32; o <<= 1) {
            const int y = __shfl_up_sync(0xffffffffu, w, o);
            if (lane >= o) w += y;
        }
        warp_sums[lane] = w;
    }
    __syncthreads();
    const int thread_excl = x - sum + (wid > 0 ? warp_sums[wid - 1] : 0);
    #pragma unroll
    for (int k = 0; k < 10; k++) {
        const int n = base + k;
        if (n < NN) {
            const int o = thread_excl + local[k];
            g_off[n] = o;
            g_cur[n] = o;
        }
    }
    if (tid == 1023) g_off[NN] = thread_excl + sum;
}

__global__ void csr_scatter_kernel(const int* __restrict__ ei)
{
    const int e = blockIdx.x * blockDim.x + threadIdx.x;
    if (e >= ET) return;
    int s, d; edge_sd(ei, e, s, d);
    if (!valid_nd(s, d)) return;
    const int pos = atomicAdd(&g_cur[d], 1);
    g_eid[pos] = e;
}

// ---------------- 3xTF32 tensor-core GEMM, 3-stage cp.async ring ------------
// (R15 body; ONE change: all fragments hoisted, mmas issued TERM-MAJOR so
//  consecutive mmas target distinct accumulators — no HMMA RAW stalls.)
// C[M,N] = A[M,K] @ op(B).  TRANSB=false: B[K,N]; true: B[N,K] (C = A@B^T).
// ACT: 0=none, 1=sigmoid.  K % 16 == 0.  split-K via blockIdx.z.

__device__ __forceinline__ uint32_t f2tf32(float f)
{
    uint32_t r;
    asm("cvt.rna.tf32.f32 %0, %1;" : "=r"(r) : "f"(f));
    return r;
}

__device__ __forceinline__ void mma_tf32(float4& d,
    uint32_t a0, uint32_t a1, uint32_t a2, uint32_t a3,
    uint32_t b0, uint32_t b1)
{
    asm volatile(
        "mma.sync.aligned.m16n8k8.row.col.f32.tf32.tf32.f32 "
        "{%0,%1,%2,%3},{%4,%5,%6,%7},{%8,%9},{%0,%1,%2,%3};"
        : "+f"(d.x), "+f"(d.y), "+f"(d.z), "+f"(d.w)
        : "r"(a0), "r"(a1), "r"(a2), "r"(a3), "r"(b0), "r"(b1));
}

__device__ __forceinline__ void cp16(uint32_t dst, const void* src, int sz)
{
    asm volatile("cp.async.ca.shared.global [%0], [%1], 16, %2;"
                 :: "r"(dst), "l"(src), "r"(sz));
}

#define PA 20
#define PB 136
#define STG 5120                        // floats per stage (A 2560 + B 2560)
#define GEMM_SMEM_BYTES (3 * STG * 4)   // 61440

template<int ACT, bool TRANSB>
__global__ __launch_bounds__(256, 2)
void gemm_tf32(int M, int N, int K,
               const float* __restrict__ A,
               const float* __restrict__ B,
               float* __restrict__ C,
               int tBase, int tRem)
{
    extern __shared__ float smem[];

    const int tid  = threadIdx.x;
    const int lane = tid & 31;
    const int warp = tid >> 5;
    const int warpM = (warp >> 2) * 64;
    const int warpN = (warp & 3) * 32;
    const int rowBase = blockIdx.y * 128;
    const int colBase = blockIdx.x * 128;

    const int z   = blockIdx.z;
    const int myT = tBase + (z < tRem ? 1 : 0);
    const int t0  = z * tBase + (z < tRem ? z : tRem);
    if (gridDim.z > 1) C += (size_t)z * M * N;

    float4 acc[4][4];
    #pragma unroll
    for (int i = 0; i < 4; i++)
        #pragma unroll
        for (int j = 0; j < 4; j++) acc[i][j] = make_float4(0.f, 0.f, 0.f, 0.f);

    auto issue_tile = [&](int t, int stage) {
        float* Ad = smem + stage * STG;
        float* Bd = Ad + 2560;
        const int k0 = t << 4;
        // A: 128 rows x 16 k = 512 16B-chunks; 2 per thread
        #pragma unroll
        for (int c = 0; c < 2; c++) {
            const int chunk = tid * 2 + c;
            const int row   = chunk >> 2;
            const int kc    = (chunk & 3) << 2;
            const float* src = A + (size_t)(rowBase + row) * K + k0 + kc;
            const uint32_t dst =
                (uint32_t)__cvta_generic_to_shared(&Ad[row * PA + kc]);
            cp16(dst, src, (rowBase + row < M) ? 16 : 0);
        }
        if (!TRANSB) {
            #pragma unroll
            for (int c = 0; c < 2; c++) {
                const int chunk = tid * 2 + c;
                const int kr = chunk >> 5;
                const int nc = (chunk & 31) << 2;
                const float* src = B + (size_t)(k0 + kr) * N + colBase + nc;
                const uint32_t dst =
                    (uint32_t)__cvta_generic_to_shared(&Bd[kr * PB + nc]);
                cp16(dst, src, (colBase + nc < N) ? 16 : 0);
            }
        } else {
            #pragma unroll
            for (int c = 0; c < 2; c++) {
                const int chunk = tid * 2 + c;
                const int row = chunk >> 2;
                const int kc  = (chunk & 3) << 2;
                const float* src = B + (size_t)(colBase + row) * K + k0 + kc;
                const uint32_t dst =
                    (uint32_t)__cvta_generic_to_shared(&Bd[row * PA + kc]);
                cp16(dst, src, (colBase + row < N) ? 16 : 0);
            }
        }
        asm volatile("cp.async.commit_group;");
    };

    if (myT > 0) issue_tile(t0, 0);
    if (myT > 1) issue_tile(t0 + 1, 1);

    int stage = 0;
    for (int tt = 0; tt < myT; tt++) {
        if (tt + 1 < myT) asm volatile("cp.async.wait_group 1;");
        else              asm volatile("cp.async.wait_group 0;");
        __syncthreads();
        if (tt + 2 < myT) {
            int ns = stage + 2; if (ns >= 3) ns -= 3;
            issue_tile(t0 + tt + 2, ns);
        }

        const float* __restrict__ Ab = smem + stage * STG;
        const float* __restrict__ Bb = Ab + 2560;

        #pragma unroll
        for (int s = 0; s < 2; s++) {
            const int c0 = (s << 3) + (lane & 3);
            const int c1 = c0 + 4;
            const int r0 = warpM + (lane >> 2);
            const int bc = warpN + (lane >> 2);

            // ---- hoist ALL fragments for this k8-step ----
            uint32_t ah[4][4], al[4][4];
            #pragma unroll
            for (int mi = 0; mi < 4; mi++) {
                const int rA = r0 + mi * 16;
                const float f0 = Ab[rA * PA + c0];
                const float f1 = Ab[(rA + 8) * PA + c0];
                const float f2 = Ab[rA * PA + c1];
                const float f3 = Ab[(rA + 8) * PA + c1];
                ah[mi][0] = f2tf32(f0);
                ah[mi][1] = f2tf32(f1);
                ah[mi][2] = f2tf32(f2);
                ah[mi][3] = f2tf32(f3);
                // lo passed raw: mma's operand read truncates to tf32
                al[mi][0] = __float_as_uint(f0 - __uint_as_float(ah[mi][0]));
                al[mi][1] = __float_as_uint(f1 - __uint_as_float(ah[mi][1]));
                al[mi][2] = __float_as_uint(f2 - __uint_as_float(ah[mi][2]));
                al[mi][3] = __float_as_uint(f3 - __uint_as_float(ah[mi][3]));
            }
            uint32_t bh[4][2], bl[4][2];
            #pragma unroll
            for (int ni = 0; ni < 4; ni++) {
                const int cB = bc + ni * 8;
                const float g0 = TRANSB ? Bb[cB * PA + c0] : Bb[c0 * PB + cB];
                const float g1 = TRANSB ? Bb[cB * PA + c1] : Bb[c1 * PB + cB];
                bh[ni][0] = f2tf32(g0);
                bh[ni][1] = f2tf32(g1);
                bl[ni][0] = __float_as_uint(g0 - __uint_as_float(bh[ni][0]));
                bl[ni][1] = __float_as_uint(g1 - __uint_as_float(bh[ni][1]));
            }

            // ---- term-major mma stream: consecutive mmas hit distinct acc --
            #pragma unroll
            for (int ni = 0; ni < 4; ni++)
                #pragma unroll
                for (int mi = 0; mi < 4; mi++)
                    mma_tf32(acc[mi][ni], ah[mi][0], ah[mi][1], ah[mi][2], ah[mi][3],
                             bl[ni][0], bl[ni][1]);
            #pragma unroll
            for (int ni = 0; ni < 4; ni++)
                #pragma unroll
                for (int mi = 0; mi < 4; mi++)
                    mma_tf32(acc[mi][ni], al[mi][0], al[mi][1], al[mi][2], al[mi][3],
                             bh[ni][0], bh[ni][1]);
            #pragma unroll
            for (int ni = 0; ni < 4; ni++)
                #pragma unroll
                for (int mi = 0; mi < 4; mi++)
                    mma_tf32(acc[mi][ni], ah[mi][0], ah[mi][1], ah[mi][2], ah[mi][3],
                             bh[ni][0], bh[ni][1]);
        }
        if (++stage >= 3) stage -= 3;
    }

    // ---- epilogue ----
    #pragma unroll
    for (int mi = 0; mi < 4; mi++) {
        const int r = rowBase + warpM + mi * 16 + (lane >> 2);
        #pragma unroll
        for (int ni = 0; ni < 4; ni++) {
            const int c = colBase + warpN + ni * 8 + 2 * (lane & 3);
            float v0 = acc[mi][ni].x, v1 = acc[mi][ni].y;
            float v2 = acc[mi][ni].z, v3 = acc[mi][ni].w;
            if (ACT == 1) {
                v0 = 1.f / (1.f + __expf(-v0));
                v1 = 1.f / (1.f + __expf(-v1));
                v2 = 1.f / (1.f + __expf(-v2));
                v3 = 1.f / (1.f + __expf(-v3));
            }
            if (r < M) {
                if (c < N)     C[(size_t)r * N + c]     = v0;
                if (c + 1 < N) C[(size_t)r * N + c + 1] = v1;
            }
            if (r + 8 < M) {
                if (c < N)     C[(size_t)(r + 8) * N + c]     = v2;
                if (c + 1 < N) C[(size_t)(r + 8) * N + c + 1] = v3;
            }
        }
    }
}

// ---- split-K combine: outp = sum_z g_part[z] (fixed order, deterministic) --
__global__ void combine_kernel(float* __restrict__ outp, int nsplit)
{
    const size_t n4 = (size_t)NN * HF / 4;
    const size_t i = (size_t)blockIdx.x * blockDim.x + threadIdx.x;
    if (i >= n4) return;
    const float4* p = reinterpret_cast<const float4*>(g_part);
    float4 s = p[i];
    for (int z = 1; z < nsplit; z++) {
        const float4 v = p[i + (size_t)z * n4];
        s.x += v.x; s.y += v.y; s.z += v.z; s.w += v.w;
    }
    reinterpret_cast<float4*>(outp)[i] = s;
}

// ---------------- final z copy (very last launch) ---------------------------
__global__ void copy_z_kernel(const float* __restrict__ z, float* __restrict__ dst)
{
    const int i = blockIdx.x * blockDim.x + threadIdx.x;
    if (i < NN * FF / 4)
        reinterpret_cast<float4*>(dst)[i] =
            reinterpret_cast<const float4*>(z)[i];
}

// --------- per-node attention logits ----------------------------------------
__global__ void attn_logits_kernel(const float* __restrict__ hp,
                                   const float* __restrict__ a_src,
                                   const float* __restrict__ a_dst)
{
    const int warp = (blockIdx.x * blockDim.x + threadIdx.x) >> 5;
    const int lane = threadIdx.x & 31;
    if (warp >= NN * HH) return;
    const int n = warp / HH, h = warp % HH;
    const float* hv = hp + (size_t)n * HF + h * FF;
    float s1 = 0.f, s2 = 0.f;
    #pragma unroll
    for (int j = 0; j < 4; j++) {
        const int f = lane + 32 * j;
        const float v = hv[f];
        s1 = fmaf(v, a_src[h * FF + f], s1);
        s2 = fmaf(v, a_dst[h * FF + f], s2);
    }
    #pragma unroll
    for (int o = 16; o; o >>= 1) {
        s1 += __shfl_xor_sync(0xffffffffu, s1, o);
        s2 += __shfl_xor_sync(0xffffffffu, s2, o);
    }
    if (lane == 0) { g_als[warp] = s1; g_ald[warp] = s2; }
}

// ---------------- fused per-dst-node softmax + aggregate --------------------
__global__ __launch_bounds__(128)
void fused_agg_kernel(const int* __restrict__ ei,
                      const float* __restrict__ b,
                      float* __restrict__ out, int act)
{
    const int n   = blockIdx.x;
    const int tid = threadIdx.x;
    const int lane = tid & 31, wid = tid >> 5;
    const int off = g_off[n];
    const int deg = g_off[n + 1] - off;

    __shared__ float warp_red[4][4];
    __shared__ float smax[4], sinv[4];
    __shared__ float alpha_sm[128][4];
    __shared__ int   ssrc_sm[128];
    __shared__ float feat[HF];

    const float4 ald4 = *reinterpret_cast<const float4*>(&g_ald[n * 4]);

    float mx[4] = { -INFINITY, -INFINITY, -INFINITY, -INFINITY };
    for (int i = tid; i < deg; i += 128) {
        const int e = g_eid[off + i];
        int s, d; edge_sd(ei, e, s, d);
        const float4 as4 = *reinterpret_cast<const float4*>(&g_als[s * 4]);
        float v[4] = { as4.x + ald4.x, as4.y + ald4.y,
                       as4.z + ald4.z, as4.w + ald4.w };
        #pragma unroll
        for (int h = 0; h < 4; h++) {
            v[h] = v[h] > 0.f ? v[h] : SLOPE * v[h];
            mx[h] = fmaxf(mx[h], v[h]);
        }
        *reinterpret_cast<float4*>(&g_eval[(size_t)(off + i) * 4]) =
            make_float4(v[0], v[1], v[2], v[3]);
    }
    #pragma unroll
    for (int h = 0; h < 4; h++)
        #pragma unroll
        for (int o = 16; o; o >>= 1)
            mx[h] = fmaxf(mx[h], __shfl_xor_sync(0xffffffffu, mx[h], o));
    if (lane == 0)
        #pragma unroll
        for (int h = 0; h < 4; h++) warp_red[wid][h] = mx[h];
    __syncthreads();
    if (tid == 0) {
        #pragma unroll
        for (int h = 0; h < 4; h++)
            smax[h] = fmaxf(fmaxf(warp_red[0][h], warp_red[1][h]),
                            fmaxf(warp_red[2][h], warp_red[3][h]));
    }
    __syncthreads();

    float sm[4] = { 0.f, 0.f, 0.f, 0.f };
    const float m0 = smax[0], m1 = smax[1], m2 = smax[2], m3 = smax[3];
    for (int i = tid; i < deg; i += 128) {
        float4 v = *reinterpret_cast<const float4*>(&g_eval[(size_t)(off + i) * 4]);
        v.x = __expf(v.x - m0); v.y = __expf(v.y - m1);
        v.z = __expf(v.z - m2); v.w = __expf(v.w - m3);
        *reinterpret_cast<float4*>(&g_eval[(size_t)(off + i) * 4]) = v;
        sm[0] += v.x; sm[1] += v.y; sm[2] += v.z; sm[3] += v.w;
    }
    #pragma unroll
    for (int h = 0; h < 4; h++)
        #pragma unroll
        for (int o = 16; o; o >>= 1)
            sm[h] += __shfl_xor_sync(0xffffffffu, sm[h], o);
    if (lane == 0)
        #pragma unroll
        for (int h = 0; h < 4; h++) warp_red[wid][h] = sm[h];
    __syncthreads();
    if (tid == 0) {
        #pragma unroll
        for (int h = 0; h < 4; h++) {
            const float t = warp_red[0][h] + warp_red[1][h] +
                            warp_red[2][h] + warp_red[3][h];
            sinv[h] = (t > 0.f) ? 1.f / t : 0.f;
        }
    }
    __syncthreads();

    const int myh = tid >> 5;
    const float i0 = sinv[0], i1 = sinv[1], i2 = sinv[2], i3 = sinv[3];
    float4 acc = make_float4(0.f, 0.f, 0.f, 0.f);
    for (int base = 0; base < deg; base += 128) {
        const int cnt = min(128, deg - base);
        __syncthreads();
        if (tid < cnt) {
            const int e = g_eid[off + base + tid];
            int s, d; edge_sd(ei, e, s, d);
            ssrc_sm[tid] = s;
            const float4 v =
                *reinterpret_cast<const float4*>(&g_eval[(size_t)(off + base + tid) * 4]);
            alpha_sm[tid][0] = v.x * i0;
            alpha_sm[tid][1] = v.y * i1;
            alpha_sm[tid][2] = v.z * i2;
            alpha_sm[tid][3] = v.w * i3;
        }
        __syncthreads();
        for (int j = 0; j < cnt; j++) {
            const int s = ssrc_sm[j];
            const float a = alpha_sm[j][myh];
            const float4 hv = *reinterpret_cast<const float4*>(
                &g_hp[(size_t)s * HF + tid * 4]);
            acc.x = fmaf(a, hv.x, acc.x);
            acc.y = fmaf(a, hv.y, acc.y);
            acc.z = fmaf(a, hv.z, acc.z);
            acc.w = fmaf(a, hv.w, acc.w);
        }
    }
    *reinterpret_cast<float4*>(&feat[tid * 4]) = acc;
    __syncthreads();

    {
        const int f = tid;
        float v = (feat[f] + feat[FF + f] + feat[2 * FF + f] + feat[3 * FF + f])
                  * 0.25f + b[f];
        v = (act == 0) ? fmaxf(v, 0.f) : tanhf(v);
        out[(size_t)n * FF + f] = v;
    }
}

// ---------------------------------------------------------------------------
extern "C" void kernel_launch(void* const* d_in, const int* in_sizes, int n_in,
                              void* d_out, int out_size)
{
    cudaFuncSetAttribute(gemm_tf32<0, false>,
                         cudaFuncAttributeMaxDynamicSharedMemorySize, GEMM_SMEM_BYTES);
    cudaFuncSetAttribute(gemm_tf32<1, true>,
                         cudaFuncAttributeMaxDynamicSharedMemorySize, GEMM_SMEM_BYTES);

    // ---- size-based input classification ----------------------------------
    const int SZ_X  = NN * NN;
    const int SZ_EI = 2 * EE;
    const int SZ_W0 = NN * HF;
    const int SZ_W  = FF * HF;
    const int SZ_A  = HH * FF;
    const int SZ_B  = FF;

    const float* x  = nullptr;
    const int*   ei = nullptr;
    const float* W [4] = {nullptr, nullptr, nullptr, nullptr};
    const float* AS[4] = {nullptr, nullptr, nullptr, nullptr};
    const float* AD[4] = {nullptr, nullptr, nullptr, nullptr};
    const float* B [4] = {nullptr, nullptr, nullptr, nullptr};

    int wIdx = 1, bIdx = 0;
    int aPos[8]; const float* aPtr[8]; int nA = 0;

    for (int i = 0; i < n_in; i++) {
        const int s = in_sizes[i];
        if      (s == SZ_X)  x = (const float*)d_in[i];
        else if (s == SZ_EI) ei = (const int*)d_in[i];
        else if (s == SZ_W0) W[0] = (const float*)d_in[i];
        else if (s == SZ_W)  { if (wIdx < 4) W[wIdx++] = (const float*)d_in[i]; }
        else if (s == SZ_A)  { if (nA < 8) { aPos[nA] = i; aPtr[nA] = (const float*)d_in[i]; nA++; } }
        else if (s == SZ_B)  { if (bIdx < 4) B[bIdx++] = (const float*)d_in[i]; }
    }

    bool contiguous8 = (nA == 8);
    for (int i = 1; i < nA; i++)
        if (aPos[i] != aPos[0] + i) { contiguous8 = false; break; }

    if (contiguous8) {
        for (int i = 0; i < 4; i++) { AS[i] = aPtr[i]; AD[i] = aPtr[4 + i]; }
    } else {
        for (int i = 0; i < 4; i++) { AS[i] = aPtr[2 * i]; AD[i] = aPtr[2 * i + 1]; }
    }

    float* hp;   cudaGetSymbolAddress((void**)&hp,   g_hp);
    float* xbuf; cudaGetSymbolAddress((void**)&xbuf, g_x);
    float* zbuf; cudaGetSymbolAddress((void**)&zbuf, g_z);
    float* part; cudaGetSymbolAddress((void**)&part, g_part);

    float* out = (float*)d_out;
    const long long need = (long long)NN * NN + (long long)NN * FF;
    float* ztail = ((long long)out_size >= need) ? out + (size_t)NN * NN : nullptr;

    // layer-0 split-K: T=625 tiles over SPLITK=8 -> tBase=78, tRem=1
    const int T0 = NN / 16;                 // 625
    const int tBase0 = T0 / SPLITK;         // 78
    const int tRem0  = T0 % SPLITK;         // 1
    // small layers: T=8 over SPLITK_S=2 -> tBase=4, tRem=0
    const int Ts = FF / 16;                 // 8
    const int tBaseS = Ts / SPLITK_S;       // 4

    // launch order: layer-0 GEMM is the 4th launch (ncu capture)
    detect_ei_kernel<<<1, 256>>>(ei);
    csr_zero_kernel <<<(NN + 255) / 256, 256>>>();
    csr_hist_kernel <<<(ET + 255) / 256, 256>>>(ei);
    {
        dim3 grid((HF + 127) / 128, (NN + 127) / 128, SPLITK);
        gemm_tf32<0, false><<<grid, 256, GEMM_SMEM_BYTES>>>(NN, HF, NN, x, W[0],
                                                            part, tBase0, tRem0);
    }
    combine_kernel<<<(NN * HF / 4 + 255) / 256, 256>>>(hp, SPLITK);

    csr_scan_kernel   <<<1, 1024>>>();
    csr_scatter_kernel<<<(ET + 255) / 256, 256>>>(ei);

    attn_logits_kernel<<<(NN * HH * 32 + 255) / 256, 256>>>(hp, AS[0], AD[0]);
    fused_agg_kernel<<<NN, 128>>>(ei, B[0], xbuf, 0);

    // layers 1-3 (K=128, split-K 2)
    for (int l = 1; l <= 3; l++) {
        dim3 grid((HF + 127) / 128, (NN + 127) / 128, SPLITK_S);
        gemm_tf32<0, false><<<grid, 256, GEMM_SMEM_BYTES>>>(NN, HF, FF, xbuf, W[l],
                                                            part, tBaseS, 0);
        combine_kernel<<<(NN * HF / 4 + 255) / 256, 256>>>(hp, SPLITK_S);
        attn_logits_kernel<<<(NN * HH * 32 + 255) / 256, 256>>>(hp, AS[l], AD[l]);
        fused_agg_kernel<<<NN, 128>>>(ei, B[l],
                                      (l == 3) ? zbuf : xbuf,
                                      (l == 3) ? 1 : 0);
    }

    // decode: adj = sigmoid(z @ z^T)
    {
        dim3 grid((NN + 127) / 128, (NN + 127) / 128, 1);
        gemm_tf32<1, true><<<grid, 256, GEMM_SMEM_BYTES>>>(NN, NN, FF, zbuf, zbuf,
                                                           out, Ts, 0);
    }

    // final: copy canonical z into the output tail
    if (ztail)
        copy_z_kernel<<<(NN * FF / 4 + 255) / 256, 256>>>(zbuf, ztail);
}

// round 17
// speedup vs baseline: 1.1075x; 1.1075x over previous
#include <cuda_runtime.h>
#include <math.h>
#include <stdint.h>

#define NN    10000
#define HH    4
#define FF    128
#define HF    (HH*FF)      // 512
#define EE    320000
#define ET    (EE+NN)      // 330000 edges incl self-loops
#define SLOPE 0.2f
#define SPLITK 8
#define SPLITK_S 2

// ---------------- scratch (device globals; no allocation allowed) ----------
__device__ float g_hp  [(size_t)NN*HF];   // projected features [N,H,F]
__device__ float g_x   [(size_t)NN*FF];   // inter-layer features [N,F]
__device__ float g_z   [(size_t)NN*FF];   // encoder output z [N,F]
__device__ float g_als [NN*HH];
__device__ float g_ald [NN*HH];
__device__ float g_eval[(size_t)ET*HH];   // per-edge exp values (CSR order)
__device__ int   g_is64;                  // edge_index dtype flag
// CSR by destination node
__device__ int   g_deg [NN];
__device__ int   g_off [NN+1];
__device__ int   g_cur [NN];
__device__ int   g_eid [ET];
// split-K partial sums
__device__ float g_part[(size_t)SPLITK*NN*HF];

// --------- edge-index dtype sniffer ----------------------------------------
__global__ void detect_ei_kernel(const int* __restrict__ ei32)
{
    __shared__ int any;
    if (threadIdx.x == 0) any = 0;
    __syncthreads();
    for (int i = threadIdx.x; i < 4096; i += blockDim.x)
        if (ei32[2 * i + 1] != 0) atomicOr(&any, 1);
    __syncthreads();
    if (threadIdx.x == 0) g_is64 = (any == 0);
}

__device__ __forceinline__ void edge_sd(const int* __restrict__ ei32, int e,
                                        int& s, int& d)
{
    if (e >= EE) { s = d = e - EE; return; }          // self-loop
    if (g_is64) { s = ei32[2 * e]; d = ei32[2 * (EE + e)]; }
    else        { s = ei32[e];     d = ei32[EE + e]; }
}

__device__ __forceinline__ bool valid_nd(int s, int d)
{
    return ((unsigned)s < NN) && ((unsigned)d < NN);
}

// ---------------- CSR construction ------------------------------------------
__global__ void csr_zero_kernel()
{
    const int n = blockIdx.x * blockDim.x + threadIdx.x;
    if (n < NN) g_deg[n] = 0;
}

__global__ void csr_hist_kernel(const int* __restrict__ ei)
{
    const int e = blockIdx.x * blockDim.x + threadIdx.x;
    if (e >= ET) return;
    int s, d; edge_sd(ei, e, s, d);
    if (valid_nd(s, d)) atomicAdd(&g_deg[d], 1);
}

__global__ void csr_scan_kernel()
{
    __shared__ int warp_sums[32];
    const int tid  = threadIdx.x;          // 1024 threads
    const int lane = tid & 31, wid = tid >> 5;
    const int base = tid * 10;

    int local[10];
    int sum = 0;
    #pragma unroll
    for (int k = 0; k < 10; k++) {
        const int n = base + k;
        const int v = (n < NN) ? g_deg[n] : 0;
        local[k] = sum;
        sum += v;
    }
    int x = sum;
    #pragma unroll
    for (int o = 1; o < 32; o <<= 1) {
        const int y = __shfl_up_sync(0xffffffffu, x, o);
        if (lane >= o) x += y;
    }
    if (lane == 31) warp_sums[wid] = x;
    __syncthreads();
    if (wid == 0) {
        int w = warp_sums[lane];
        #pragma unroll
        for (int o = 1; o < 32; o <<= 1) {
            const int y = __shfl_up_sync(0xffffffffu, w, o);
            if (lane >= o) w += y;
        }
        warp_sums[lane] = w;
    }
    __syncthreads();
    const int thread_excl = x - sum + (wid > 0 ? warp_sums[wid - 1] : 0);
    #pragma unroll
    for (int k = 0; k < 10; k++) {
        const int n = base + k;
        if (n < NN) {
            const int o = thread_excl + local[k];
            g_off[n] = o;
            g_cur[n] = o;
        }
    }
    if (tid == 1023) g_off[NN] = thread_excl + sum;
}

__global__ void csr_scatter_kernel(const int* __restrict__ ei)
{
    const int e = blockIdx.x * blockDim.x + threadIdx.x;
    if (e >= ET) return;
    int s, d; edge_sd(ei, e, s, d);
    if (!valid_nd(s, d)) return;
    const int pos = atomicAdd(&g_cur[d], 1);
    g_eid[pos] = e;
}

// ---------------- 3xTF32 tensor-core GEMM, 3-stage cp.async ring ------------
// (R15 body.  SYM=1 (decode only): upper-triangle blocks, mirrored store.)
// C[M,N] = A[M,K] @ op(B).  TRANSB=false: B[K,N]; true: B[N,K] (C = A@B^T).
// ACT: 0=none, 1=sigmoid.  K % 16 == 0.  split-K via blockIdx.z.

__device__ __forceinline__ uint32_t f2tf32(float f)
{
    uint32_t r;
    asm("cvt.rna.tf32.f32 %0, %1;" : "=r"(r) : "f"(f));
    return r;
}

__device__ __forceinline__ void mma_tf32(float4& d,
    uint32_t a0, uint32_t a1, uint32_t a2, uint32_t a3,
    uint32_t b0, uint32_t b1)
{
    asm volatile(
        "mma.sync.aligned.m16n8k8.row.col.f32.tf32.tf32.f32 "
        "{%0,%1,%2,%3},{%4,%5,%6,%7},{%8,%9},{%0,%1,%2,%3};"
        : "+f"(d.x), "+f"(d.y), "+f"(d.z), "+f"(d.w)
        : "r"(a0), "r"(a1), "r"(a2), "r"(a3), "r"(b0), "r"(b1));
}

__device__ __forceinline__ void cp16(uint32_t dst, const void* src, int sz)
{
    asm volatile("cp.async.ca.shared.global [%0], [%1], 16, %2;"
                 :: "r"(dst), "l"(src), "r"(sz));
}

#define PA 20
#define PB 136
#define STG 5120                        // floats per stage (A 2560 + B 2560)
#define GEMM_SMEM_BYTES (3 * STG * 4)   // 61440
#define TSP 73                          // transpose staging stride (coprime 32)

template<int ACT, bool TRANSB, int SYM>
__global__ __launch_bounds__(256, 2)
void gemm_tf32(int M, int N, int K,
               const float* __restrict__ A,
               const float* __restrict__ B,
               float* __restrict__ C,
               int tBase, int tRem)
{
    extern __shared__ float smem[];

    if (SYM && blockIdx.y > blockIdx.x) return;   // lower triangle: mirrored

    const int tid  = threadIdx.x;
    const int lane = tid & 31;
    const int warp = tid >> 5;
    const int warpM = (warp >> 2) * 64;
    const int warpN = (warp & 3) * 32;
    const int rowBase = blockIdx.y * 128;
    const int colBase = blockIdx.x * 128;

    const int z   = blockIdx.z;
    const int myT = tBase + (z < tRem ? 1 : 0);
    const int t0  = z * tBase + (z < tRem ? z : tRem);
    if (gridDim.z > 1) C += (size_t)z * M * N;

    float4 acc[4][4];
    #pragma unroll
    for (int i = 0; i < 4; i++)
        #pragma unroll
        for (int j = 0; j < 4; j++) acc[i][j] = make_float4(0.f, 0.f, 0.f, 0.f);

    auto issue_tile = [&](int t, int stage) {
        float* Ad = smem + stage * STG;
        float* Bd = Ad + 2560;
        const int k0 = t << 4;
        #pragma unroll
        for (int c = 0; c < 2; c++) {
            const int chunk = tid * 2 + c;
            const int row   = chunk >> 2;
            const int kc    = (chunk & 3) << 2;
            const float* src = A + (size_t)(rowBase + row) * K + k0 + kc;
            const uint32_t dst =
                (uint32_t)__cvta_generic_to_shared(&Ad[row * PA + kc]);
            cp16(dst, src, (rowBase + row < M) ? 16 : 0);
        }
        if (!TRANSB) {
            #pragma unroll
            for (int c = 0; c < 2; c++) {
                const int chunk = tid * 2 + c;
                const int kr = chunk >> 5;
                const int nc = (chunk & 31) << 2;
                const float* src = B + (size_t)(k0 + kr) * N + colBase + nc;
                const uint32_t dst =
                    (uint32_t)__cvta_generic_to_shared(&Bd[kr * PB + nc]);
                cp16(dst, src, (colBase + nc < N) ? 16 : 0);
            }
        } else {
            #pragma unroll
            for (int c = 0; c < 2; c++) {
                const int chunk = tid * 2 + c;
                const int row = chunk >> 2;
                const int kc  = (chunk & 3) << 2;
                const float* src = B + (size_t)(colBase + row) * K + k0 + kc;
                const uint32_t dst =
                    (uint32_t)__cvta_generic_to_shared(&Bd[row * PA + kc]);
                cp16(dst, src, (colBase + row < N) ? 16 : 0);
            }
        }
        asm volatile("cp.async.commit_group;");
    };

    if (myT > 0) issue_tile(t0, 0);
    if (myT > 1) issue_tile(t0 + 1, 1);

    int stage = 0;
    for (int tt = 0; tt < myT; tt++) {
        if (tt + 1 < myT) asm volatile("cp.async.wait_group 1;");
        else              asm volatile("cp.async.wait_group 0;");
        __syncthreads();
        if (tt + 2 < myT) {
            int ns = stage + 2; if (ns >= 3) ns -= 3;
            issue_tile(t0 + tt + 2, ns);
        }

        const float* __restrict__ Ab = smem + stage * STG;
        const float* __restrict__ Bb = Ab + 2560;

        #pragma unroll
        for (int s = 0; s < 2; s++) {
            const int c0 = (s << 3) + (lane & 3);
            const int c1 = c0 + 4;
            const int r0 = warpM + (lane >> 2);
            const int bc = warpN + (lane >> 2);

            uint32_t ah[4][4], al[4][4];
            #pragma unroll
            for (int mi = 0; mi < 4; mi++) {
                const int rA = r0 + mi * 16;
                const float f0 = Ab[rA * PA + c0];
                const float f1 = Ab[(rA + 8) * PA + c0];
                const float f2 = Ab[rA * PA + c1];
                const float f3 = Ab[(rA + 8) * PA + c1];
                ah[mi][0] = f2tf32(f0);
                ah[mi][1] = f2tf32(f1);
                ah[mi][2] = f2tf32(f2);
                ah[mi][3] = f2tf32(f3);
                al[mi][0] = __float_as_uint(f0 - __uint_as_float(ah[mi][0]));
                al[mi][1] = __float_as_uint(f1 - __uint_as_float(ah[mi][1]));
                al[mi][2] = __float_as_uint(f2 - __uint_as_float(ah[mi][2]));
                al[mi][3] = __float_as_uint(f3 - __uint_as_float(ah[mi][3]));
            }
            #pragma unroll
            for (int ni = 0; ni < 4; ni++) {
                const int cB = bc + ni * 8;
                const float g0 = TRANSB ? Bb[cB * PA + c0] : Bb[c0 * PB + cB];
                const float g1 = TRANSB ? Bb[cB * PA + c1] : Bb[c1 * PB + cB];
                const uint32_t bh0 = f2tf32(g0);
                const uint32_t bh1 = f2tf32(g1);
                const uint32_t bl0 = __float_as_uint(g0 - __uint_as_float(bh0));
                const uint32_t bl1 = __float_as_uint(g1 - __uint_as_float(bh1));
                #pragma unroll
                for (int mi = 0; mi < 4; mi++) {
                    mma_tf32(acc[mi][ni], ah[mi][0], ah[mi][1], ah[mi][2], ah[mi][3],
                             bl0, bl1);
                    mma_tf32(acc[mi][ni], al[mi][0], al[mi][1], al[mi][2], al[mi][3],
                             bh0, bh1);
                    mma_tf32(acc[mi][ni], ah[mi][0], ah[mi][1], ah[mi][2], ah[mi][3],
                             bh0, bh1);
                }
            }
        }
        if (++stage >= 3) stage -= 3;
    }

    // ---- activation in place ----
    if (ACT == 1) {
        #pragma unroll
        for (int mi = 0; mi < 4; mi++)
            #pragma unroll
            for (int ni = 0; ni < 4; ni++) {
                acc[mi][ni].x = 1.f / (1.f + __expf(-acc[mi][ni].x));
                acc[mi][ni].y = 1.f / (1.f + __expf(-acc[mi][ni].y));
                acc[mi][ni].z = 1.f / (1.f + __expf(-acc[mi][ni].z));
                acc[mi][ni].w = 1.f / (1.f + __expf(-acc[mi][ni].w));
            }
    }

    // ---- normal (coalesced) store ----
    #pragma unroll
    for (int mi = 0; mi < 4; mi++) {
        const int r = rowBase + warpM + mi * 16 + (lane >> 2);
        #pragma unroll
        for (int ni = 0; ni < 4; ni++) {
            const int c = colBase + warpN + ni * 8 + 2 * (lane & 3);
            if (r < M) {
                if (c < N)     C[(size_t)r * N + c]     = acc[mi][ni].x;
                if (c + 1 < N) C[(size_t)r * N + c + 1] = acc[mi][ni].y;
            }
            if (r + 8 < M) {
                if (c < N)     C[(size_t)(r + 8) * N + c]     = acc[mi][ni].z;
                if (c + 1 < N) C[(size_t)(r + 8) * N + c + 1] = acc[mi][ni].w;
            }
        }
    }

    // ---- mirrored store for symmetric decode (off-diagonal blocks) ----
    if (SYM && blockIdx.x != blockIdx.y) {
        float* ts = smem;                     // reuse ring smem: 128*TSP floats
        #pragma unroll
        for (int p = 0; p < 2; p++) {
            __syncthreads();                  // protect prior contents
            if ((warpN < 64) == (p == 0)) {   // warps whose cols are in this half
                #pragma unroll
                for (int mi = 0; mi < 4; mi++) {
                    const int rl = warpM + mi * 16 + (lane >> 2);
                    #pragma unroll
                    for (int ni = 0; ni < 4; ni++) {
                        const int cl = warpN + ni * 8 + 2 * (lane & 3) - 64 * p;
                        ts[rl * TSP + cl]           = acc[mi][ni].x;
                        ts[rl * TSP + cl + 1]       = acc[mi][ni].y;
                        ts[(rl + 8) * TSP + cl]     = acc[mi][ni].z;
                        ts[(rl + 8) * TSP + cl + 1] = acc[mi][ni].w;
                    }
                }
            }
            __syncthreads();
            // write rows of C^T: 64 rows x 128 cols = 2048 float4, 8/thread
            #pragma unroll
            for (int i = 0; i < 8; i++) {
                const int chunk = tid * 8 + i;
                const int cl = chunk >> 5;            // 0..63
                const int rq = chunk & 31;            // float4 index along r
                const int gr = colBase + 64 * p + cl; // mirrored row
                const int gc = rowBase + rq * 4;      // mirrored col base
                if (gr < N) {
                    const float v0 = ts[(rq * 4 + 0) * TSP + cl];
                    const float v1 = ts[(rq * 4 + 1) * TSP + cl];
                    const float v2 = ts[(rq * 4 + 2) * TSP + cl];
                    const float v3 = ts[(rq * 4 + 3) * TSP + cl];
                    if (gc + 3 < M) {
                        *reinterpret_cast<float4*>(&C[(size_t)gr * N + gc]) =
                            make_float4(v0, v1, v2, v3);
                    } else {
                        if (gc + 0 < M) C[(size_t)gr * N + gc + 0] = v0;
                        if (gc + 1 < M) C[(size_t)gr * N + gc + 1] = v1;
                        if (gc + 2 < M) C[(size_t)gr * N + gc + 2] = v2;
                        if (gc + 3 < M) C[(size_t)gr * N + gc + 3] = v3;
                    }
                }
            }
        }
    }
}

// ---- fused split-K combine + attention logits (block per node) -------------
// Sums partials into hp[n][*] and computes als/ald[n][h] in one pass.
// 128 threads: thread t owns elems t*4..t*4+3; warp w == head w.
__global__ __launch_bounds__(128)
void combine_attn_kernel(float* __restrict__ hp,
                         const float* __restrict__ a_src,
                         const float* __restrict__ a_dst,
                         int nsplit)
{
    const int n    = blockIdx.x;
    const int tid  = threadIdx.x;
    const int lane = tid & 31;
    const int h    = tid >> 5;
    const size_t stride4 = (size_t)NN * HF / 4;
    const size_t base4   = (size_t)n * (HF / 4) + tid;

    const float4* p = reinterpret_cast<const float4*>(g_part);
    float4 s = p[base4];
    for (int z = 1; z < nsplit; z++) {
        const float4 v = p[base4 + (size_t)z * stride4];
        s.x += v.x; s.y += v.y; s.z += v.z; s.w += v.w;
    }
    reinterpret_cast<float4*>(hp)[base4] = s;

    const int f = lane * 4;                 // feature offset within head
    const float4 as4 = *reinterpret_cast<const float4*>(&a_src[h * FF + f]);
    const float4 ad4 = *reinterpret_cast<const float4*>(&a_dst[h * FF + f]);
    float s1 = s.x * as4.x + s.y * as4.y + s.z * as4.z + s.w * as4.w;
    float s2 = s.x * ad4.x + s.y * ad4.y + s.z * ad4.z + s.w * ad4.w;
    #pragma unroll
    for (int o = 16; o; o >>= 1) {
        s1 += __shfl_xor_sync(0xffffffffu, s1, o);
        s2 += __shfl_xor_sync(0xffffffffu, s2, o);
    }
    if (lane == 0) { g_als[n * 4 + h] = s1; g_ald[n * 4 + h] = s2; }
}

// ---------------- final z copy (very last launch) ---------------------------
__global__ void copy_z_kernel(const float* __restrict__ z, float* __restrict__ dst)
{
    const int i = blockIdx.x * blockDim.x + threadIdx.x;
    if (i < NN * FF / 4)
        reinterpret_cast<float4*>(dst)[i] =
            reinterpret_cast<const float4*>(z)[i];
}

// ---------------- fused per-dst-node softmax + aggregate --------------------
__global__ __launch_bounds__(128)
void fused_agg_kernel(const int* __restrict__ ei,
                      const float* __restrict__ b,
                      float* __restrict__ out, int act)
{
    const int n   = blockIdx.x;
    const int tid = threadIdx.x;
    const int lane = tid & 31, wid = tid >> 5;
    const int off = g_off[n];
    const int deg = g_off[n + 1] - off;

    __shared__ float warp_red[4][4];
    __shared__ float smax[4], sinv[4];
    __shared__ float alpha_sm[128][4];
    __shared__ int   ssrc_sm[128];
    __shared__ float feat[HF];

    const float4 ald4 = *reinterpret_cast<const float4*>(&g_ald[n * 4]);

    float mx[4] = { -INFINITY, -INFINITY, -INFINITY, -INFINITY };
    for (int i = tid; i < deg; i += 128) {
        const int e = g_eid[off + i];
        int s, d; edge_sd(ei, e, s, d);
        const float4 as4 = *reinterpret_cast<const float4*>(&g_als[s * 4]);
        float v[4] = { as4.x + ald4.x, as4.y + ald4.y,
                       as4.z + ald4.z, as4.w + ald4.w };
        #pragma unroll
        for (int h = 0; h < 4; h++) {
            v[h] = v[h] > 0.f ? v[h] : SLOPE * v[h];
            mx[h] = fmaxf(mx[h], v[h]);
        }
        *reinterpret_cast<float4*>(&g_eval[(size_t)(off + i) * 4]) =
            make_float4(v[0], v[1], v[2], v[3]);
    }
    #pragma unroll
    for (int h = 0; h < 4; h++)
        #pragma unroll
        for (int o = 16; o; o >>= 1)
            mx[h] = fmaxf(mx[h], __shfl_xor_sync(0xffffffffu, mx[h], o));
    if (lane == 0)
        #pragma unroll
        for (int h = 0; h < 4; h++) warp_red[wid][h] = mx[h];
    __syncthreads();
    if (tid == 0) {
        #pragma unroll
        for (int h = 0; h < 4; h++)
            smax[h] = fmaxf(fmaxf(warp_red[0][h], warp_red[1][h]),
                            fmaxf(warp_red[2][h], warp_red[3][h]));
    }
    __syncthreads();

    float sm[4] = { 0.f, 0.f, 0.f, 0.f };
    const float m0 = smax[0], m1 = smax[1], m2 = smax[2], m3 = smax[3];
    for (int i = tid; i < deg; i += 128) {
        float4 v = *reinterpret_cast<const float4*>(&g_eval[(size_t)(off + i) * 4]);
        v.x = __expf(v.x - m0); v.y = __expf(v.y - m1);
        v.z = __expf(v.z - m2); v.w = __expf(v.w - m3);
        *reinterpret_cast<float4*>(&g_eval[(size_t)(off + i) * 4]) = v;
        sm[0] += v.x; sm[1] += v.y; sm[2] += v.z; sm[3] += v.w;
    }
    #pragma unroll
    for (int h = 0; h < 4; h++)
        #pragma unroll
        for (int o = 16; o; o >>= 1)
            sm[h] += __shfl_xor_sync(0xffffffffu, sm[h], o);
    if (lane == 0)
        #pragma unroll
        for (int h = 0; h < 4; h++) warp_red[wid][h] = sm[h];
    __syncthreads();
    if (tid == 0) {
        #pragma unroll
        for (int h = 0; h < 4; h++) {
            const float t = warp_red[0][h] + warp_red[1][h] +
                            warp_red[2][h] + warp_red[3][h];
            sinv[h] = (t > 0.f) ? 1.f / t : 0.f;
        }
    }
    __syncthreads();

    const int myh = tid >> 5;
    const float i0 = sinv[0], i1 = sinv[1], i2 = sinv[2], i3 = sinv[3];
    float4 acc = make_float4(0.f, 0.f, 0.f, 0.f);
    for (int base = 0; base < deg; base += 128) {
        const int cnt = min(128, deg - base);
        __syncthreads();
        if (tid < cnt) {
            const int e = g_eid[off + base + tid];
            int s, d; edge_sd(ei, e, s, d);
            ssrc_sm[tid] = s;
            const float4 v =
                *reinterpret_cast<const float4*>(&g_eval[(size_t)(off + base + tid) * 4]);
            alpha_sm[tid][0] = v.x * i0;
            alpha_sm[tid][1] = v.y * i1;
            alpha_sm[tid][2] = v.z * i2;
            alpha_sm[tid][3] = v.w * i3;
        }
        __syncthreads();
        for (int j = 0; j < cnt; j++) {
            const int s = ssrc_sm[j];
            const float a = alpha_sm[j][myh];
            const float4 hv = *reinterpret_cast<const float4*>(
                &g_hp[(size_t)s * HF + tid * 4]);
            acc.x = fmaf(a, hv.x, acc.x);
            acc.y = fmaf(a, hv.y, acc.y);
            acc.z = fmaf(a, hv.z, acc.z);
            acc.w = fmaf(a, hv.w, acc.w);
        }
    }
    *reinterpret_cast<float4*>(&feat[tid * 4]) = acc;
    __syncthreads();

    {
        const int f = tid;
        float v = (feat[f] + feat[FF + f] + feat[2 * FF + f] + feat[3 * FF + f])
                  * 0.25f + b[f];
        v = (act == 0) ? fmaxf(v, 0.f) : tanhf(v);
        out[(size_t)n * FF + f] = v;
    }
}

// ---------------------------------------------------------------------------
extern "C" void kernel_launch(void* const* d_in, const int* in_sizes, int n_in,
                              void* d_out, int out_size)
{
    cudaFuncSetAttribute(gemm_tf32<0, false, 0>,
                         cudaFuncAttributeMaxDynamicSharedMemorySize, GEMM_SMEM_BYTES);
    cudaFuncSetAttribute(gemm_tf32<1, true, 1>,
                         cudaFuncAttributeMaxDynamicSharedMemorySize, GEMM_SMEM_BYTES);

    // ---- size-based input classification ----------------------------------
    const int SZ_X  = NN * NN;
    const int SZ_EI = 2 * EE;
    const int SZ_W0 = NN * HF;
    const int SZ_W  = FF * HF;
    const int SZ_A  = HH * FF;
    const int SZ_B  = FF;

    const float* x  = nullptr;
    const int*   ei = nullptr;
    const float* W [4] = {nullptr, nullptr, nullptr, nullptr};
    const float* AS[4] = {nullptr, nullptr, nullptr, nullptr};
    const float* AD[4] = {nullptr, nullptr, nullptr, nullptr};
    const float* B [4] = {nullptr, nullptr, nullptr, nullptr};

    int wIdx = 1, bIdx = 0;
    int aPos[8]; const float* aPtr[8]; int nA = 0;

    for (int i = 0; i < n_in; i++) {
        const int s = in_sizes[i];
        if      (s == SZ_X)  x = (const float*)d_in[i];
        else if (s == SZ_EI) ei = (const int*)d_in[i];
        else if (s == SZ_W0) W[0] = (const float*)d_in[i];
        else if (s == SZ_W)  { if (wIdx < 4) W[wIdx++] = (const float*)d_in[i]; }
        else if (s == SZ_A)  { if (nA < 8) { aPos[nA] = i; aPtr[nA] = (const float*)d_in[i]; nA++; } }
        else if (s == SZ_B)  { if (bIdx < 4) B[bIdx++] = (const float*)d_in[i]; }
    }

    bool contiguous8 = (nA == 8);
    for (int i = 1; i < nA; i++)
        if (aPos[i] != aPos[0] + i) { contiguous8 = false; break; }

    if (contiguous8) {
        for (int i = 0; i < 4; i++) { AS[i] = aPtr[i]; AD[i] = aPtr[4 + i]; }
    } else {
        for (int i = 0; i < 4; i++) { AS[i] = aPtr[2 * i]; AD[i] = aPtr[2 * i + 1]; }
    }

    float* hp;   cudaGetSymbolAddress((void**)&hp,   g_hp);
    float* xbuf; cudaGetSymbolAddress((void**)&xbuf, g_x);
    float* zbuf; cudaGetSymbolAddress((void**)&zbuf, g_z);
    float* part; cudaGetSymbolAddress((void**)&part, g_part);

    float* out = (float*)d_out;
    const long long need = (long long)NN * NN + (long long)NN * FF;
    float* ztail = ((long long)out_size >= need) ? out + (size_t)NN * NN : nullptr;

    // layer-0 split-K: T=625 tiles over SPLITK=8 -> tBase=78, tRem=1
    const int T0 = NN / 16;                 // 625
    const int tBase0 = T0 / SPLITK;         // 78
    const int tRem0  = T0 % SPLITK;         // 1
    // small layers: T=8 over SPLITK_S=2 -> tBase=4, tRem=0
    const int Ts = FF / 16;                 // 8
    const int tBaseS = Ts / SPLITK_S;       // 4

    // launch order: layer-0 GEMM is the 4th launch (ncu capture)
    detect_ei_kernel<<<1, 256>>>(ei);
    csr_zero_kernel <<<(NN + 255) / 256, 256>>>();
    csr_hist_kernel <<<(ET + 255) / 256, 256>>>(ei);
    {
        dim3 grid((HF + 127) / 128, (NN + 127) / 128, SPLITK);
        gemm_tf32<0, false, 0><<<grid, 256, GEMM_SMEM_BYTES>>>(NN, HF, NN, x, W[0],
                                                               part, tBase0, tRem0);
    }
    csr_scan_kernel   <<<1, 1024>>>();
    csr_scatter_kernel<<<(ET + 255) / 256, 256>>>(ei);

    combine_attn_kernel<<<NN, 128>>>(hp, AS[0], AD[0], SPLITK);
    fused_agg_kernel<<<NN, 128>>>(ei, B[0], xbuf, 0);

    // layers 1-3 (K=128, split-K 2)
    for (int l = 1; l <= 3; l++) {
        dim3 grid((HF + 127) / 128, (NN + 127) / 128, SPLITK_S);
        gemm_tf32<0, false, 0><<<grid, 256, GEMM_SMEM_BYTES>>>(NN, HF, FF, xbuf, W[l],
                                                               part, tBaseS, 0);
        combine_attn_kernel<<<NN, 128>>>(hp, AS[l], AD[l], SPLITK_S);
        fused_agg_kernel<<<NN, 128>>>(ei, B[l],
                                      (l == 3) ? zbuf : xbuf,
                                      (l == 3) ? 1 : 0);
    }

    // decode: adj = sigmoid(z @ z^T), symmetric — upper triangle + mirror
    {
        dim3 grid((NN + 127) / 128, (NN + 127) / 128, 1);
        gemm_tf32<1, true, 1><<<grid, 256, GEMM_SMEM_BYTES>>>(NN, NN, FF, zbuf, zbuf,
                                                              out, Ts, 0);
    }

    // final: copy canonical z into the output tail
    if (ztail)
        copy_z_kernel<<<(NN * FF / 4 + 255) / 256, 256>>>(zbuf, ztail);
}